// round 7
// baseline (speedup 1.0000x reference)
#include <cuda_runtime.h>
#include <cuda_bf16.h>
#include <cstdint>

// Problem shape (fixed for this registry entry)
#define B     8
#define T     200
#define U1    101        // U+1
#define V     1024
#define UD    104        // padded u-stride in diagonal-major layout (26 x 16B rows)
#define ND    300        // number of diagonals (T + U1 - 1)
#define PADR  16         // pad rows after the last batch (prefetch overrun)
#define R4    (UD / 4)   // 26 uint4 per diagonal row
#define LN2   0.6931471805599453f

// Diagonal-major packed scores: g_sc[b][d][u] = bf16x2( Bl, Lc ) where
//   Bl = exp(blank[t-1,u])  (neutral 1.0 if t<1 or cell invalid)
//   Lc = exp(lab  [t,  u])  (neutral 0.0 if u<1 or cell invalid),  t = d-u
__device__ __align__(16) __nv_bfloat162 g_sc[(B * ND + PADR) * UD];

// ---------------------------------------------------------------------------
// Kernel 1: gather + exponentiate the 2 useful channels of the 662MB logits
// tensor into a diagonal-major bf16x2 table with neutral pads (branch-free DP).
// Also fills the prefetch-overrun pad rows and zero-inits the scalar output.
// ---------------------------------------------------------------------------
__global__ void gather_kernel(const float* __restrict__ logits,
                              const int* __restrict__ labels,
                              float* __restrict__ out) {
    int idx = blockIdx.x * blockDim.x + threadIdx.x;
    if (idx == 0) out[0] = 0.0f;
    if (idx >= (B * ND + PADR) * UD) return;

    float bl = 1.0f, lc = 0.0f;                    // neutral: a' = a*1 + left*0
    if (idx < B * ND * UD) {
        int u = idx % UD;
        int d = (idx / UD) % ND;
        int b = idx / (UD * ND);
        int t = d - u;
        if (u < U1 && t >= 0 && t < T) {
            if (t >= 1)
                bl = __expf(logits[((long)(b * T + (t - 1)) * U1 + u) * V]);
            if (u >= 1) {
                int lab = labels[b * (U1 - 1) + (u - 1)];
                lc = __expf(logits[((long)(b * T + t) * U1 + (u - 1)) * V + lab]);
            }
        }
    }
    g_sc[idx] = __floats2bfloat162_rn(bl, lc);
}

// ---------------------------------------------------------------------------
// Kernel 2: one 32-thread CTA per batch, linear-domain wavefront:
//   A[t,u] = A[t-1,u]*Bl + A[t,u-1]*Lc
// lane L owns u = 4L..4L+3; lefts are registers, 1 shfl/diag.
// Scores are read straight from L2 (written by gather) via LDG.128 into two
// explicit 16-row register blocks, double-buffered: block n+1 prefetched while
// block n computes (MLP=16, L2 latency hidden). Exact power-of-2 renorm via
// one redux.sync per 16 diagonals. The final block snapshots the state at
// step capRem, so overrun steps need no predication.
// ---------------------------------------------------------------------------
struct DPState { float a0, a1, a2, a3; };

__device__ __forceinline__ void dp_step_v(DPState& s, uint4 cur, int lsrc) {
    float l0 = __shfl_sync(0xffffffffu, s.a3, lsrc);   // lane-1 prev-diag a3
    const __nv_bfloat162* c = (const __nv_bfloat162*)&cur;
    float2 f0 = __bfloat1622float2(c[0]);
    float2 f1 = __bfloat1622float2(c[1]);
    float2 f2 = __bfloat1622float2(c[2]);
    float2 f3 = __bfloat1622float2(c[3]);
    float o0 = s.a0, o1 = s.a1, o2 = s.a2;             // prev-diagonal lefts
    s.a0 = fmaf(s.a0, f0.x, l0 * f0.y);
    s.a1 = fmaf(s.a1, f1.x, o0 * f1.y);
    s.a2 = fmaf(s.a2, f2.x, o1 * f2.y);
    s.a3 = fmaf(s.a3, f3.x, o2 * f3.y);
}

__device__ __forceinline__ void renorm(DPState& s, int& S) {
    float mx = fmaxf(fmaxf(s.a0, s.a1), fmaxf(s.a2, s.a3));
    // a >= 0 always -> unsigned bit-pattern order == float order
    unsigned mxi = __reduce_max_sync(0xffffffffu, (unsigned)__float_as_int(mx));
    int e = (int)(mxi >> 23) - 127;
    float sc = __int_as_float((127 - e) << 23);        // 2^-e, exact
    s.a0 *= sc; s.a1 *= sc; s.a2 *= sc; s.a3 *= sc;
    S += e;
}

__global__ void __launch_bounds__(32, 1)
dp_kernel(const int* __restrict__ loglen,
          const int* __restrict__ lablen,
          float* __restrict__ out) {
    const int b    = blockIdx.x;
    const int lane = threadIdx.x;
    const int lsrc = (lane + 31) & 31;

    const int Tb     = loglen[b];
    const int Lb     = lablen[b];
    const int nSteps = Tb + Lb;                    // diags 0..capD inclusive
    const int capD   = nSteps - 1;
    const int blkTot = (nSteps + 15) >> 4;         // >= 10 for this shape
    const int nFull  = blkTot - 1;                 // fast blocks
    const int capRem = capD - nFull * 16;          // 0..15, snapshot step

    // lane's 16B slice of diagonal row r lives at gp[r * R4]
    const uint4* gp = reinterpret_cast<const uint4*>(g_sc)
                      + (size_t)(b * ND) * R4 + lane;

    DPState s;
    s.a0 = (lane == 0) ? 1.0f : 0.0f;              // A[.,u=0] seed (exp(0)=1)
    s.a1 = 0.0f; s.a2 = 0.0f; s.a3 = 0.0f;
    int S = 0;
    float c0 = 0.0f, c1 = 0.0f, c2 = 0.0f, c3 = 0.0f;

    uint4 bufA[16], bufB[16];

    auto pref = [&](uint4 (&buf)[16], int blkIdx) {
        const uint4* q = gp + blkIdx * 16 * R4;
        #pragma unroll
        for (int k = 0; k < 16; ++k)
            buf[k] = q[k * R4];
    };
    auto comp = [&](uint4 (&buf)[16]) {
        #pragma unroll
        for (int k = 0; k < 16; ++k)
            dp_step_v(s, buf[k], lsrc);
    };
    auto compLast = [&](uint4 (&buf)[16]) {
        #pragma unroll
        for (int k = 0; k < 16; ++k) {
            dp_step_v(s, buf[k], lsrc);
            if (k == capRem) { c0 = s.a0; c1 = s.a1; c2 = s.a2; c3 = s.a3; }
        }
    };

    pref(bufA, 0);
    int blk = 0;
    #pragma unroll 1
    while (blk + 2 <= nFull) {
        pref(bufB, blk + 1); renorm(s, S); comp(bufA);
        pref(bufA, blk + 2); renorm(s, S); comp(bufB);
        blk += 2;
    }
    if (blk == nFull) {                            // nFull even: last in A
        renorm(s, S); compLast(bufA);
    } else {                                       // blk == nFull-1: last in B
        pref(bufB, blk + 1); renorm(s, S); comp(bufA);
        renorm(s, S); compLast(bufB);
    }

    if (lane == (Lb >> 2)) {
        int ck = Lb & 3;
        float cap = (ck == 0) ? c0 : (ck == 1) ? c1 : (ck == 2) ? c2 : c3;
        float loss = -(log2f(cap) + (float)S) * LN2;   // back to nats
        atomicAdd(out, loss * (1.0f / B));             // mean over batch
    }
}

// ---------------------------------------------------------------------------
extern "C" void kernel_launch(void* const* d_in, const int* in_sizes, int n_in,
                              void* d_out, int out_size) {
    const float* logits = (const float*)d_in[0];
    const int*   labels = (const int*)d_in[1];
    const int*   loglen = (const int*)d_in[2];
    const int*   lablen = (const int*)d_in[3];
    float* out = (float*)d_out;

    const int total = (B * ND + PADR) * UD;        // includes pad rows

    gather_kernel<<<(total + 255) / 256, 256>>>(logits, labels, out);
    dp_kernel<<<B, 32>>>(loglen, lablen, out);
}